// round 2
// baseline (speedup 1.0000x reference)
#include <cuda_runtime.h>

#define N_NODES 500000
#define N_EDGES 4000000

// ---- scratch (device globals; no allocation allowed) ----
__device__ int    g_cnt[N_NODES];
__device__ float4 g_y[N_NODES];      // {dinv*x0, dinv*x1, dinv*x2, dinv}
__device__ float4 g_agg1[N_NODES];   // accumulated neighbor sums (3 used)
__device__ float  g_s[N_NODES];      // dinv * (relu(h1) @ W2)
__device__ float  g_agg2[N_NODES];

// ---- K0: zero degree counters ----
__global__ void k_zero_cnt() {
    int i = blockIdx.x * blockDim.x + threadIdx.x;
    if (i < N_NODES) g_cnt[i] = 0;
}

// ---- K1: degree count over edge targets (int4-vectorized) ----
__global__ void k_count(const int* __restrict__ col) {
    int i = blockIdx.x * blockDim.x + threadIdx.x;
    if (i < N_EDGES / 4) {
        int4 c = reinterpret_cast<const int4*>(col)[i];
        atomicAdd(&g_cnt[c.x], 1);
        atomicAdd(&g_cnt[c.y], 1);
        atomicAdd(&g_cnt[c.z], 1);
        atomicAdd(&g_cnt[c.w], 1);
    }
}

// ---- K2: dinv = rsqrt(deg), y = dinv*x, agg1 init = self-loop term ----
__global__ void k_prep(const float* __restrict__ x) {
    int v = blockIdx.x * blockDim.x + threadIdx.x;
    if (v < N_NODES) {
        // deg includes the +1 self-loop; always >= 1
        float d = rsqrtf((float)(g_cnt[v] + 1));
        float x0 = x[3 * v + 0];
        float x1 = x[3 * v + 1];
        float x2 = x[3 * v + 2];
        float4 y = make_float4(d * x0, d * x1, d * x2, d);
        g_y[v]    = y;  // gather source (w carries dinv)
        g_agg1[v] = y;  // self-loop: dinv[v]*x[v] already included
    }
}

// ---- K3: edge scatter, layer 1 (3-dim input space) ----
__global__ void k_scatter1(const int* __restrict__ row, const int* __restrict__ col) {
    int e = blockIdx.x * blockDim.x + threadIdx.x;
    if (e < N_EDGES) {
        int r = row[e];
        int c = col[e];
        float4 y = g_y[r];
        float* a = reinterpret_cast<float*>(&g_agg1[c]);
        atomicAdd(a + 0, y.x);
        atomicAdd(a + 1, y.y);
        atomicAdd(a + 2, y.z);
    }
}

// ---- K4: fused node MLP: h1 = relu((dinv*agg1) @ W1 + b1); s = dinv*(h1 @ W2) ----
__global__ void k_mlp(const float* __restrict__ W1, const float* __restrict__ b1,
                      const float* __restrict__ W2) {
    __shared__ float sW1[48];  // [3][16] row-major
    __shared__ float sb1[16];
    __shared__ float sW2[16];
    int t = threadIdx.x;
    if (t < 48) sW1[t] = W1[t];
    if (t < 16) { sb1[t] = b1[t]; sW2[t] = W2[t]; }
    __syncthreads();

    int v = blockIdx.x * blockDim.x + t;
    if (v < N_NODES) {
        float4 a = g_agg1[v];
        float  d = g_y[v].w;
        float t0 = d * a.x, t1 = d * a.y, t2 = d * a.z;
        float acc = 0.0f;
#pragma unroll
        for (int j = 0; j < 16; j++) {
            float h = fmaf(t0, sW1[j],
                      fmaf(t1, sW1[16 + j],
                      fmaf(t2, sW1[32 + j], sb1[j])));
            acc = fmaf(fmaxf(h, 0.0f), sW2[j], acc);
        }
        float s = d * acc;
        g_s[v]    = s;  // gather source for layer 2
        g_agg2[v] = s;  // self-loop term included
    }
}

// ---- K5: edge scatter, layer 2 (scalar) ----
__global__ void k_scatter2(const int* __restrict__ row, const int* __restrict__ col) {
    int e = blockIdx.x * blockDim.x + threadIdx.x;
    if (e < N_EDGES) {
        int r = row[e];
        int c = col[e];
        atomicAdd(&g_agg2[c], g_s[r]);
    }
}

// ---- K6: finalize: out = dinv*agg2 + b2 ----
__global__ void k_final(float* __restrict__ out, const float* __restrict__ b2) {
    int v = blockIdx.x * blockDim.x + threadIdx.x;
    if (v < N_NODES) {
        out[v] = fmaf(g_y[v].w, g_agg2[v], b2[0]);
    }
}

extern "C" void kernel_launch(void* const* d_in, const int* in_sizes, int n_in,
                              void* d_out, int out_size) {
    const float* x   = (const float*)d_in[0];
    const int*   ei  = (const int*)d_in[1];   // [2][E]: row = ei, col = ei + E
    const float* W1  = (const float*)d_in[2]; // [3][16]
    const float* b1  = (const float*)d_in[3]; // [16]
    const float* W2  = (const float*)d_in[4]; // [16][1]
    const float* b2  = (const float*)d_in[5]; // [1]
    float* out = (float*)d_out;

    const int* row = ei;
    const int* col = ei + N_EDGES;

    const int T = 256;
    const int nb_nodes = (N_NODES + T - 1) / T;
    const int nb_edges = (N_EDGES + T - 1) / T;
    const int nb_cnt   = (N_EDGES / 4 + T - 1) / T;

    k_zero_cnt<<<nb_nodes, T>>>();
    k_count<<<nb_cnt, T>>>(col);
    k_prep<<<nb_nodes, T>>>(x);
    k_scatter1<<<nb_edges, T>>>(row, col);
    k_mlp<<<nb_nodes, T>>>(W1, b1, W2);
    k_scatter2<<<nb_edges, T>>>(row, col);
    k_final<<<nb_nodes, T>>>(out, b2);
}

// round 3
// speedup vs baseline: 1.3351x; 1.3351x over previous
#include <cuda_runtime.h>

#define N_NODES 500000
#define N_EDGES 4000000

// ---- scratch (device globals; no allocation allowed) ----
__device__ int    g_cnt[N_NODES];
__device__ float4 g_y[N_NODES];      // {dinv*x0, dinv*x1, dinv*x2, dinv}
__device__ float4 g_agg1[N_NODES];   // accumulated neighbor sums (xyz used, w junk)
__device__ float  g_s[N_NODES];      // dinv * (relu(h1) @ W2)
__device__ float  g_agg2[N_NODES];

// ---- K0: zero degree counters ----
__global__ void k_zero_cnt() {
    int i = blockIdx.x * blockDim.x + threadIdx.x;
    if (i < N_NODES) g_cnt[i] = 0;
}

// ---- K1: degree count over edge targets (int4-vectorized) ----
__global__ void k_count(const int* __restrict__ col) {
    int i = blockIdx.x * blockDim.x + threadIdx.x;
    if (i < N_EDGES / 4) {
        int4 c = reinterpret_cast<const int4*>(col)[i];
        atomicAdd(&g_cnt[c.x], 1);
        atomicAdd(&g_cnt[c.y], 1);
        atomicAdd(&g_cnt[c.z], 1);
        atomicAdd(&g_cnt[c.w], 1);
    }
}

// ---- K2: dinv = rsqrt(deg), y = dinv*x, agg1 init = self-loop term ----
__global__ void k_prep(const float* __restrict__ x) {
    int v = blockIdx.x * blockDim.x + threadIdx.x;
    if (v < N_NODES) {
        float d = rsqrtf((float)(g_cnt[v] + 1));  // +1 self-loop
        float x0 = x[3 * v + 0];
        float x1 = x[3 * v + 1];
        float x2 = x[3 * v + 2];
        float4 y = make_float4(d * x0, d * x1, d * x2, d);
        g_y[v]    = y;  // gather source (w carries dinv)
        g_agg1[v] = y;  // self-loop term pre-seeded
    }
}

// ---- K3: edge scatter, layer 1: ONE float4 atomic per edge ----
__global__ void k_scatter1(const int* __restrict__ row, const int* __restrict__ col) {
    int i = blockIdx.x * blockDim.x + threadIdx.x;
    if (i < N_EDGES / 4) {
        int4 r = reinterpret_cast<const int4*>(row)[i];
        int4 c = reinterpret_cast<const int4*>(col)[i];
        atomicAdd(&g_agg1[c.x], g_y[r.x]);
        atomicAdd(&g_agg1[c.y], g_y[r.y]);
        atomicAdd(&g_agg1[c.z], g_y[r.z]);
        atomicAdd(&g_agg1[c.w], g_y[r.w]);
    }
}

// ---- K4: fused node MLP: h1 = relu((dinv*agg1) @ W1 + b1); s = dinv*(h1 @ W2) ----
__global__ void k_mlp(const float* __restrict__ W1, const float* __restrict__ b1,
                      const float* __restrict__ W2) {
    __shared__ float sW1[48];  // [3][16] row-major
    __shared__ float sb1[16];
    __shared__ float sW2[16];
    int t = threadIdx.x;
    if (t < 48) sW1[t] = W1[t];
    if (t < 16) { sb1[t] = b1[t]; sW2[t] = W2[t]; }
    __syncthreads();

    int v = blockIdx.x * blockDim.x + t;
    if (v < N_NODES) {
        float4 a = g_agg1[v];
        float  d = g_y[v].w;
        float t0 = d * a.x, t1 = d * a.y, t2 = d * a.z;
        float acc = 0.0f;
#pragma unroll
        for (int j = 0; j < 16; j++) {
            float h = fmaf(t0, sW1[j],
                      fmaf(t1, sW1[16 + j],
                      fmaf(t2, sW1[32 + j], sb1[j])));
            acc = fmaf(fmaxf(h, 0.0f), sW2[j], acc);
        }
        float s = d * acc;
        g_s[v]    = s;  // gather source for layer 2
        g_agg2[v] = s;  // self-loop term included
    }
}

// ---- K5: edge scatter, layer 2 (scalar), int4-vectorized indices ----
__global__ void k_scatter2(const int* __restrict__ row, const int* __restrict__ col) {
    int i = blockIdx.x * blockDim.x + threadIdx.x;
    if (i < N_EDGES / 4) {
        int4 r = reinterpret_cast<const int4*>(row)[i];
        int4 c = reinterpret_cast<const int4*>(col)[i];
        atomicAdd(&g_agg2[c.x], g_s[r.x]);
        atomicAdd(&g_agg2[c.y], g_s[r.y]);
        atomicAdd(&g_agg2[c.z], g_s[r.z]);
        atomicAdd(&g_agg2[c.w], g_s[r.w]);
    }
}

// ---- K6: finalize: out = dinv*agg2 + b2 ----
__global__ void k_final(float* __restrict__ out, const float* __restrict__ b2) {
    int v = blockIdx.x * blockDim.x + threadIdx.x;
    if (v < N_NODES) {
        out[v] = fmaf(g_y[v].w, g_agg2[v], b2[0]);
    }
}

extern "C" void kernel_launch(void* const* d_in, const int* in_sizes, int n_in,
                              void* d_out, int out_size) {
    const float* x   = (const float*)d_in[0];
    const int*   ei  = (const int*)d_in[1];   // [2][E]: row = ei, col = ei + E
    const float* W1  = (const float*)d_in[2]; // [3][16]
    const float* b1  = (const float*)d_in[3]; // [16]
    const float* W2  = (const float*)d_in[4]; // [16][1]
    const float* b2  = (const float*)d_in[5]; // [1]
    float* out = (float*)d_out;

    const int* row = ei;
    const int* col = ei + N_EDGES;

    const int T = 256;
    const int nb_nodes = (N_NODES + T - 1) / T;
    const int nb_e4    = (N_EDGES / 4 + T - 1) / T;

    k_zero_cnt<<<nb_nodes, T>>>();
    k_count<<<nb_e4, T>>>(col);
    k_prep<<<nb_nodes, T>>>(x);
    k_scatter1<<<nb_e4, T>>>(row, col);
    k_mlp<<<nb_nodes, T>>>(W1, b1, W2);
    k_scatter2<<<nb_e4, T>>>(row, col);
    k_final<<<nb_nodes, T>>>(out, b2);
}